// round 6
// baseline (speedup 1.0000x reference)
#include <cuda_runtime.h>
#include <math.h>

#define B_ 32
#define T_ 1024
#define J_ 256
#define D_ 512

// ---------------- scratch (static device globals; no allocation) ------------
__device__ float g_S[B_ * T_ * J_];   // 33.5 MB: S, then exp(S - M_j) (unnormalized)
__device__ float g_a[B_ * T_];        // ctx . w1
__device__ float g_c[B_ * J_];        // q . w2
__device__ float g_m[B_ * T_];        // rowmax over j
__device__ float g_bt[B_ * T_];       // softmax_t(rowmax)
__device__ float g_h[B_ * D_];        // sum_t bt * ctx
__device__ float g_zinv[B_ * J_];     // 1 / sum_t exp(S - M_j)

// ---------------- tf32 helpers ----------------------------------------------
__device__ __forceinline__ float tf32r(float x) {
    unsigned u;
    asm("cvt.rna.tf32.f32 %0, %1;" : "=r"(u) : "f"(x));
    return __uint_as_float(u);
}

#define MMA_TF32(c, af, b2)                                                     \
    asm("mma.sync.aligned.m16n8k8.row.col.f32.tf32.tf32.f32 "                   \
        "{%0,%1,%2,%3},{%4,%5,%6,%7},{%8,%9},{%0,%1,%2,%3};"                    \
        : "+f"((c)[0]), "+f"((c)[1]), "+f"((c)[2]), "+f"((c)[3])                \
        : "r"(__float_as_uint((af).x)), "r"(__float_as_uint((af).y)),           \
          "r"(__float_as_uint((af).z)), "r"(__float_as_uint((af).w)),           \
          "r"(__float_as_uint((b2).x)), "r"(__float_as_uint((b2).y)))

// ---------------- kernel 1: a = ctx.w1, c = q.w2 ----------------------------
__global__ __launch_bounds__(256) void dotw_kernel(const float* __restrict__ ctx,
                                                   const float* __restrict__ q,
                                                   const float* __restrict__ w) {
    int gt = blockIdx.x * 256 + threadIdx.x;
    int gw = gt >> 5;
    int lane = gt & 31;
    if (gw >= B_ * T_ + B_ * J_) return;
    const float* rp;
    const float* wp;
    float* op;
    if (gw < B_ * T_) {
        rp = ctx + (size_t)gw * D_;
        wp = w;
        op = g_a + gw;
    } else {
        int r = gw - B_ * T_;
        rp = q + (size_t)r * D_;
        wp = w + D_;
        op = g_c + r;
    }
    const float4* r4 = (const float4*)rp;
    const float4* w4 = (const float4*)wp;
    float s = 0.f;
#pragma unroll
    for (int i = 0; i < 4; i++) {
        float4 x = r4[lane + i * 32];
        float4 ww = w4[lane + i * 32];
        s += x.x * ww.x + x.y * ww.y + x.z * ww.z + x.w * ww.w;
    }
#pragma unroll
    for (int off = 16; off > 0; off >>= 1) s += __shfl_xor_sync(0xffffffffu, s, off);
    if (lane == 0) *op = s;
}

// ---------------- kernel 2: GEMM1  S = (ctx*w3) @ q^T + a + c  (tf32 mma) ---
__global__ __launch_bounds__(256) void gemm1_tc(const float* __restrict__ ctx,
                                                const float* __restrict__ q,
                                                const float* __restrict__ w) {
    __shared__ float As[4 * 8 * 128];   // [ka][matom][lane*4 + r]
    __shared__ float Bs[4 * 16 * 64];   // [ka][natom][lane*2 + r]
    __shared__ float w3s[D_];

    const int tid = threadIdx.x;
    const int b = blockIdx.z;
    const int m0 = blockIdx.y * 128;
    const int n0 = blockIdx.x * 128;
    const float* Ag = ctx + (size_t)b * T_ * D_;
    const float* Bg = q + (size_t)b * J_ * D_;

    if (tid < 128) ((float4*)w3s)[tid] = ((const float4*)(w + 2 * D_))[tid];

    const int lane = tid & 31;
    const int wid = tid >> 5;
    const int warp_m = wid & 1;
    const int warp_n = wid >> 1;

    float acc[4][4][4];
#pragma unroll
    for (int i = 0; i < 4; i++)
#pragma unroll
        for (int j = 0; j < 4; j++)
#pragma unroll
            for (int k = 0; k < 4; k++) acc[i][j][k] = 0.f;

    float4 pa[4], pb[4];
#pragma unroll
    for (int i = 0; i < 4; i++) {
        int f = tid + i * 256;
        int m = f >> 3, k4 = f & 7;
        pa[i] = *(const float4*)(Ag + (size_t)(m0 + m) * D_ + k4 * 4);
        pb[i] = *(const float4*)(Bg + (size_t)(n0 + m) * D_ + k4 * 4);
    }
    __syncthreads();  // w3s ready

    const int KT = D_ / 32;
    for (int kt = 0; kt < KT; kt++) {
#pragma unroll
        for (int i = 0; i < 4; i++) {
            int f = tid + i * 256;
            int m = f >> 3, k4 = f & 7;
            int ka = k4 >> 1;
            // A scatter (with w3 scaling)
            {
                int matom = m >> 4, mr = m & 15;
                int ls = (mr & 7) * 4;
                int r = (mr >> 3) + 2 * (k4 & 1);
                float* dst = As + ((ka * 8 + matom) << 7) + r;
#pragma unroll
                for (int j = 0; j < 4; j++)
                    dst[(ls + j) * 4] = tf32r((&pa[i].x)[j] * w3s[kt * 32 + k4 * 4 + j]);
            }
            // B scatter
            {
                int natom = m >> 3, nr = m & 7;
                int ls = nr * 4;
                int r = k4 & 1;
                float* dst = Bs + ((ka * 16 + natom) << 6) + r;
#pragma unroll
                for (int j = 0; j < 4; j++) dst[(ls + j) * 2] = tf32r((&pb[i].x)[j]);
            }
        }
        __syncthreads();
        if (kt + 1 < KT) {
#pragma unroll
            for (int i = 0; i < 4; i++) {
                int f = tid + i * 256;
                int m = f >> 3, k4 = f & 7;
                pa[i] = *(const float4*)(Ag + (size_t)(m0 + m) * D_ + (kt + 1) * 32 + k4 * 4);
                pb[i] = *(const float4*)(Bg + (size_t)(n0 + m) * D_ + (kt + 1) * 32 + k4 * 4);
            }
        }
#pragma unroll
        for (int ka = 0; ka < 4; ka++) {
            float4 af[4];
            float2 bf[4];
#pragma unroll
            for (int ma = 0; ma < 4; ma++)
                af[ma] = *(const float4*)&As[((ka * 8 + warp_m * 4 + ma) << 7) + lane * 4];
#pragma unroll
            for (int na = 0; na < 4; na++)
                bf[na] = *(const float2*)&Bs[((ka * 16 + warp_n * 4 + na) << 6) + lane * 2];
#pragma unroll
            for (int ma = 0; ma < 4; ma++)
#pragma unroll
                for (int na = 0; na < 4; na++) MMA_TF32(acc[ma][na], af[ma], bf[na]);
        }
        __syncthreads();
    }

    // epilogue: + a[b,m] + c[b,n]
    const int g = lane >> 2;
    const int tg = lane & 3;
#pragma unroll
    for (int ma = 0; ma < 4; ma++) {
        int r0 = m0 + warp_m * 64 + ma * 16 + g;
        float a0v = g_a[b * T_ + r0];
        float a1v = g_a[b * T_ + r0 + 8];
#pragma unroll
        for (int na = 0; na < 4; na++) {
            int n = n0 + warp_n * 32 + na * 8 + tg * 2;
            float c0 = g_c[b * J_ + n];
            float c1 = g_c[b * J_ + n + 1];
            float* p0 = g_S + (size_t)(b * T_ + r0) * J_ + n;
            *(float2*)p0 = make_float2(acc[ma][na][0] + a0v + c0, acc[ma][na][1] + a0v + c1);
            *(float2*)(p0 + 8 * J_) =
                make_float2(acc[ma][na][2] + a1v + c0, acc[ma][na][3] + a1v + c1);
        }
    }
}

// ---------------- kernel 3: rowmax over j -----------------------------------
__global__ __launch_bounds__(256) void rowmax_kernel() {
    int gw = (blockIdx.x * 256 + threadIdx.x) >> 5;
    int lane = threadIdx.x & 31;
    const float4* p = (const float4*)(g_S + (size_t)gw * J_);
    float4 v1 = p[lane];
    float4 v2 = p[lane + 32];
    float mx = fmaxf(fmaxf(fmaxf(v1.x, v1.y), fmaxf(v1.z, v1.w)),
                     fmaxf(fmaxf(v2.x, v2.y), fmaxf(v2.z, v2.w)));
#pragma unroll
    for (int off = 16; off > 0; off >>= 1) mx = fmaxf(mx, __shfl_xor_sync(0xffffffffu, mx, off));
    if (lane == 0) g_m[gw] = mx;
}

// ---------------- kernel 4: b_t = softmax_t(rowmax) -------------------------
__global__ __launch_bounds__(256) void bt_kernel() {
    const int b = blockIdx.x;
    const int tid = threadIdx.x;
    const int lane = tid & 31;
    const int wid = tid >> 5;
    __shared__ float redA[8], redB[8];

    float4 v = ((const float4*)(g_m + b * T_))[tid];
    float mx = fmaxf(fmaxf(v.x, v.y), fmaxf(v.z, v.w));
#pragma unroll
    for (int off = 16; off > 0; off >>= 1) mx = fmaxf(mx, __shfl_xor_sync(0xffffffffu, mx, off));
    if (lane == 0) redA[wid] = mx;
    __syncthreads();
    float bm = redA[0];
#pragma unroll
    for (int w = 1; w < 8; w++) bm = fmaxf(bm, redA[w]);

    float e0 = __expf(v.x - bm), e1 = __expf(v.y - bm);
    float e2 = __expf(v.z - bm), e3 = __expf(v.w - bm);
    float s = e0 + e1 + e2 + e3;
#pragma unroll
    for (int off = 16; off > 0; off >>= 1) s += __shfl_xor_sync(0xffffffffu, s, off);
    if (lane == 0) redB[wid] = s;
    __syncthreads();
    float tot = 0.f;
#pragma unroll
    for (int w = 0; w < 8; w++) tot += redB[w];
    float inv = 1.f / tot;
    ((float4*)(g_bt + b * T_))[tid] = make_float4(e0 * inv, e1 * inv, e2 * inv, e3 * inv);
}

// ---------------- kernel 5: column softmax over t, UNNORMALIZED -------------
// Pass 1: column max (no MUFU). Pass 2: one __expf per element, write e back,
// store 1/sum into g_zinv. Normalization is folded into GEMM2's A scatter.
// Each thread handles a float2 (2 adjacent j), 8-way split over t.
__global__ __launch_bounds__(256) void colsoftmax_kernel() {
    const int b = blockIdx.y;
    const int lane = threadIdx.x & 31;
    const int jj = blockIdx.x * 64 + lane * 2;
    const int ts = threadIdx.x >> 5;  // 0..7
    float* S = g_S + (size_t)b * T_ * J_;
    __shared__ float2 red[8][32];

    float2 mx = make_float2(-3.0e38f, -3.0e38f);
    for (int t = ts; t < T_; t += 8) {
        float2 v = *(const float2*)&S[t * J_ + jj];
        mx.x = fmaxf(mx.x, v.x);
        mx.y = fmaxf(mx.y, v.y);
    }
    red[ts][lane] = mx;
    __syncthreads();
    float2 M = red[0][lane];
#pragma unroll
    for (int r = 1; r < 8; r++) {
        float2 o = red[r][lane];
        M.x = fmaxf(M.x, o.x);
        M.y = fmaxf(M.y, o.y);
    }
    __syncthreads();

    float2 sm = make_float2(0.f, 0.f);
    for (int t = ts; t < T_; t += 8) {
        float2 v = *(const float2*)&S[t * J_ + jj];
        float ex = __expf(v.x - M.x);
        float ey = __expf(v.y - M.y);
        *(float2*)&S[t * J_ + jj] = make_float2(ex, ey);
        sm.x += ex;
        sm.y += ey;
    }
    red[ts][lane] = sm;
    __syncthreads();
    if (ts == 0) {
        float2 s = red[0][lane];
#pragma unroll
        for (int r = 1; r < 8; r++) {
            float2 o = red[r][lane];
            s.x += o.x;
            s.y += o.y;
        }
        *(float2*)&g_zinv[b * J_ + jj] = make_float2(1.f / s.x, 1.f / s.y);
    }
}

// ---------------- kernel 6: h[b,d] = sum_t bt * ctx -------------------------
__global__ __launch_bounds__(256) void h_kernel(const float* __restrict__ ctx) {
    const int b = blockIdx.y;
    const int d = blockIdx.x * 256 + threadIdx.x;
    __shared__ float bts[T_];
    for (int i = threadIdx.x; i < T_; i += 256) bts[i] = g_bt[b * T_ + i];
    __syncthreads();
    const float* cp = ctx + (size_t)b * T_ * D_ + d;
    float acc = 0.f;
#pragma unroll 4
    for (int t = 0; t < T_; t++) acc += bts[t] * cp[(size_t)t * D_];
    g_h[b * D_ + d] = acc;
}

// ---------------- kernel 7: GEMM2  U = (e * zinv) @ q, fused G assembly -----
// A = unnormalized exp stored in g_S; zinv folded in at the tf32 A-scatter.
__global__ __launch_bounds__(256) void gemm2_tc(const float* __restrict__ ctx,
                                                const float* __restrict__ q,
                                                float* __restrict__ out) {
    __shared__ float As[4 * 8 * 128];
    __shared__ float Bs[4 * 16 * 64];
    __shared__ float zs[J_];

    const int tid = threadIdx.x;
    const int b = blockIdx.z;
    const int m0 = blockIdx.y * 128;
    const int n0 = blockIdx.x * 128;
    const float* Ag = g_S + (size_t)b * T_ * J_;  // e [1024][256]
    const float* Bg = q + (size_t)b * J_ * D_;    // [256][512], n contiguous

    const int lane = tid & 31;
    const int wid = tid >> 5;
    const int warp_m = wid & 1;
    const int warp_n = wid >> 1;

    zs[tid] = g_zinv[b * J_ + tid];

    float acc[4][4][4];
#pragma unroll
    for (int i = 0; i < 4; i++)
#pragma unroll
        for (int j = 0; j < 4; j++)
#pragma unroll
            for (int k = 0; k < 4; k++) acc[i][j][k] = 0.f;

    float4 pa[4], pb[4];
#pragma unroll
    for (int i = 0; i < 4; i++) {
        int f = tid + i * 256;
        int m = f >> 3, k4 = f & 7;            // A indices
        int kb = f >> 5, n4 = f & 31;          // B indices
        pa[i] = *(const float4*)(Ag + (size_t)(m0 + m) * J_ + k4 * 4);
        pb[i] = *(const float4*)(Bg + (size_t)kb * D_ + n0 + n4 * 4);
    }
    __syncthreads();  // zs visible before first A scatter

    const int KT = J_ / 32;
    for (int kt = 0; kt < KT; kt++) {
#pragma unroll
        for (int i = 0; i < 4; i++) {
            int f = tid + i * 256;
            // A scatter (x zinv)
            {
                int m = f >> 3, k4 = f & 7;
                int ka = k4 >> 1;
                int matom = m >> 4, mr = m & 15;
                int ls = (mr & 7) * 4;
                int r = (mr >> 3) + 2 * (k4 & 1);
                float* dst = As + ((ka * 8 + matom) << 7) + r;
                const float* zp = zs + kt * 32 + k4 * 4;
#pragma unroll
                for (int j = 0; j < 4; j++) dst[(ls + j) * 4] = tf32r((&pa[i].x)[j] * zp[j]);
            }
            // B scatter: element (k, n4*4+j)
            {
                int kb = f >> 5, n4 = f & 31;
                int ka = kb >> 3, kr = kb & 7;
                int natom = n4 >> 1;
                int nr0 = (n4 & 1) * 4;
                int r = (kr >> 2);
                float* dst = Bs + ((ka * 16 + natom) << 6) + (kr & 3) * 2 + r;
#pragma unroll
                for (int j = 0; j < 4; j++) dst[(nr0 + j) * 8] = tf32r((&pb[i].x)[j]);
            }
        }
        __syncthreads();
        if (kt + 1 < KT) {
#pragma unroll
            for (int i = 0; i < 4; i++) {
                int f = tid + i * 256;
                int m = f >> 3, k4 = f & 7;
                int kb = f >> 5, n4 = f & 31;
                pa[i] = *(const float4*)(Ag + (size_t)(m0 + m) * J_ + (kt + 1) * 32 + k4 * 4);
                pb[i] = *(const float4*)(Bg + (size_t)((kt + 1) * 32 + kb) * D_ + n0 + n4 * 4);
            }
        }
#pragma unroll
        for (int ka = 0; ka < 4; ka++) {
            float4 af[4];
            float2 bf[4];
#pragma unroll
            for (int ma = 0; ma < 4; ma++)
                af[ma] = *(const float4*)&As[((ka * 8 + warp_m * 4 + ma) << 7) + lane * 4];
#pragma unroll
            for (int na = 0; na < 4; na++)
                bf[na] = *(const float2*)&Bs[((ka * 16 + warp_n * 4 + na) << 6) + lane * 2];
#pragma unroll
            for (int ma = 0; ma < 4; ma++)
#pragma unroll
                for (int na = 0; na < 4; na++) MMA_TF32(acc[ma][na], af[ma], bf[na]);
        }
        __syncthreads();
    }

    // epilogue: G = [ctx | U | ctx*U | ctx*h]
    const int g = lane >> 2;
    const int tg = lane & 3;
#pragma unroll
    for (int ma = 0; ma < 4; ma++) {
        int r0 = m0 + warp_m * 64 + ma * 16 + g;
#pragma unroll
        for (int rr = 0; rr < 2; rr++) {
            int m = r0 + rr * 8;
            const float* crow = ctx + ((size_t)(b * T_ + m)) * D_;
            float* orow = out + ((size_t)(b * T_ + m)) * (4 * D_);
#pragma unroll
            for (int na = 0; na < 4; na++) {
                int n = n0 + warp_n * 32 + na * 8 + tg * 2;
                float2 cv = *(const float2*)(crow + n);
                float2 hv = *(const float2*)(g_h + b * D_ + n);
                float u0 = acc[ma][na][rr * 2 + 0];
                float u1 = acc[ma][na][rr * 2 + 1];
                *(float2*)(orow + n) = cv;
                *(float2*)(orow + D_ + n) = make_float2(u0, u1);
                *(float2*)(orow + 2 * D_ + n) = make_float2(cv.x * u0, cv.y * u1);
                *(float2*)(orow + 3 * D_ + n) = make_float2(cv.x * hv.x, cv.y * hv.y);
            }
        }
    }
}

// ---------------- launch -----------------------------------------------------
extern "C" void kernel_launch(void* const* d_in, const int* in_sizes, int n_in,
                              void* d_out, int out_size) {
    const float* ctx = (const float*)d_in[0];
    const float* q = (const float*)d_in[1];
    const float* w = (const float*)d_in[2];
    float* out = (float*)d_out;

    dotw_kernel<<<5120, 256>>>(ctx, q, w);
    gemm1_tc<<<dim3(2, 8, 32), 256>>>(ctx, q, w);
    rowmax_kernel<<<4096, 256>>>();
    bt_kernel<<<32, 256>>>();
    colsoftmax_kernel<<<dim3(4, 32), 256>>>();
    h_kernel<<<dim3(2, 32), 256>>>(ctx);
    gemm2_tc<<<dim3(4, 8, 32), 256>>>(ctx, q, out);
}

// round 8
// speedup vs baseline: 1.3617x; 1.3617x over previous
#include <cuda_runtime.h>
#include <cstdint>
#include <math.h>

#define B_ 32
#define T_ 1024
#define J_ 256
#define D_ 512

// ---------------- scratch (static device globals; no allocation) ------------
__device__ float g_S[B_ * T_ * J_];   // S, then P (normalized column softmax)
__device__ float g_a[B_ * T_];        // ctx . w1
__device__ float g_c[B_ * J_];        // q . w2
__device__ float g_m[B_ * T_];        // rowmax over j
__device__ float g_bt[B_ * T_];       // softmax_t(rowmax)
__device__ float g_h[B_ * D_];        // sum_t bt * ctx

// ---------------- bf16 helpers ----------------------------------------------
__device__ __forceinline__ uint32_t bf2(float lo, float hi) {
    uint32_t r;
    asm("cvt.rn.bf16x2.f32 %0, %1, %2;" : "=r"(r) : "f"(hi), "f"(lo));
    return r;
}

#define MMA_BF16(c, a, bb)                                                      \
    asm("mma.sync.aligned.m16n8k16.row.col.f32.bf16.bf16.f32 "                  \
        "{%0,%1,%2,%3},{%4,%5,%6,%7},{%8,%9},{%0,%1,%2,%3};"                    \
        : "+f"((c)[0]), "+f"((c)[1]), "+f"((c)[2]), "+f"((c)[3])                \
        : "r"((a)[0]), "r"((a)[1]), "r"((a)[2]), "r"((a)[3]),                   \
          "r"((bb)[0]), "r"((bb)[1]))

// ---------------- kernel 1: a = ctx.w1, c = q.w2 ----------------------------
__global__ __launch_bounds__(256) void dotw_kernel(const float* __restrict__ ctx,
                                                   const float* __restrict__ q,
                                                   const float* __restrict__ w) {
    int gt = blockIdx.x * 256 + threadIdx.x;
    int gw = gt >> 5;
    int lane = gt & 31;
    if (gw >= B_ * T_ + B_ * J_) return;
    const float* rp;
    const float* wp;
    float* op;
    if (gw < B_ * T_) {
        rp = ctx + (size_t)gw * D_;
        wp = w;
        op = g_a + gw;
    } else {
        int r = gw - B_ * T_;
        rp = q + (size_t)r * D_;
        wp = w + D_;
        op = g_c + r;
    }
    const float4* r4 = (const float4*)rp;
    const float4* w4 = (const float4*)wp;
    float s = 0.f;
#pragma unroll
    for (int i = 0; i < 4; i++) {
        float4 x = r4[lane + i * 32];
        float4 ww = w4[lane + i * 32];
        s += x.x * ww.x + x.y * ww.y + x.z * ww.z + x.w * ww.w;
    }
#pragma unroll
    for (int off = 16; off > 0; off >>= 1) s += __shfl_xor_sync(0xffffffffu, s, off);
    if (lane == 0) *op = s;
}

// ---------------- kernel 2: GEMM1  S = (ctx*w3) @ q^T + a + c  (bf16 mma) ---
// Block 128x128, K-tile 32 (= 2 k16 steps), 256 threads = 8 warps 2(m)x4(n),
// warp tile 64x32. SMEM holds pre-permuted bf16 fragments: A frag = 1 lds.128,
// B frag = 1 lds.64, conflict-free.
__global__ __launch_bounds__(256) void gemm1_tc(const float* __restrict__ ctx,
                                                const float* __restrict__ q,
                                                const float* __restrict__ w) {
    __shared__ uint32_t As[2 * 8 * 128];   // [ka][matom][lane*4 + reg]
    __shared__ uint32_t Bs[2 * 16 * 64];   // [ka][natom][lane*2 + reg]
    __shared__ float w3s[D_];

    const int tid = threadIdx.x;
    const int b = blockIdx.z;
    const int m0 = blockIdx.y * 128;
    const int n0 = blockIdx.x * 128;
    const float* Ag = ctx + (size_t)b * T_ * D_;
    const float* Bg = q + (size_t)b * J_ * D_;

    if (tid < 128) ((float4*)w3s)[tid] = ((const float4*)(w + 2 * D_))[tid];

    const int lane = tid & 31;
    const int wid = tid >> 5;
    const int warp_m = wid & 1;
    const int warp_n = wid >> 1;

    float acc[4][4][4];
#pragma unroll
    for (int i = 0; i < 4; i++)
#pragma unroll
        for (int j = 0; j < 4; j++)
#pragma unroll
            for (int k = 0; k < 4; k++) acc[i][j][k] = 0.f;

    float4 pa[4], pb[4];
#pragma unroll
    for (int i = 0; i < 4; i++) {
        int f = tid + i * 256;
        int m = f >> 3, k4 = f & 7;
        pa[i] = *(const float4*)(Ag + (size_t)(m0 + m) * D_ + k4 * 4);
        pb[i] = *(const float4*)(Bg + (size_t)(n0 + m) * D_ + k4 * 4);
    }
    __syncthreads();  // w3s ready

    const int KT = D_ / 32;
    for (int kt = 0; kt < KT; kt++) {
#pragma unroll
        for (int i = 0; i < 4; i++) {
            int f = tid + i * 256;
            int m = f >> 3, k4 = f & 7;
            int ka = k4 >> 2;
            int kl = (k4 & 3) * 4;           // local k within k16: 0,4,8,12
            int slot = (kl >> 1) & 3;        // 0 or 2
            // A scatter (w3-scaled, bf16 packed)
            {
                float4 v = pa[i];
                const float* wp = w3s + kt * 32 + k4 * 4;
                v.x *= wp[0]; v.y *= wp[1]; v.z *= wp[2]; v.w *= wp[3];
                int r = m & 15;
                uint32_t* dst = As + ((ka * 8 + (m >> 4)) << 7) +
                                ((r & 7) * 4 + slot) * 4 + (r >> 3) + ((kl >= 8) ? 2 : 0);
                dst[0] = bf2(v.x, v.y);
                dst[4] = bf2(v.z, v.w);
            }
            // B scatter
            {
                float4 v = pb[i];
                uint32_t* dst = Bs + ((ka * 16 + (m >> 3)) << 6) +
                                ((m & 7) * 4 + slot) * 2 + ((kl >= 8) ? 1 : 0);
                dst[0] = bf2(v.x, v.y);
                dst[2] = bf2(v.z, v.w);
            }
        }
        __syncthreads();
        if (kt + 1 < KT) {
#pragma unroll
            for (int i = 0; i < 4; i++) {
                int f = tid + i * 256;
                int m = f >> 3, k4 = f & 7;
                pa[i] = *(const float4*)(Ag + (size_t)(m0 + m) * D_ + (kt + 1) * 32 + k4 * 4);
                pb[i] = *(const float4*)(Bg + (size_t)(n0 + m) * D_ + (kt + 1) * 32 + k4 * 4);
            }
        }
#pragma unroll
        for (int ka = 0; ka < 2; ka++) {
            uint32_t af[4][4], bf[4][2];
#pragma unroll
            for (int ma = 0; ma < 4; ma++)
                *(uint4*)af[ma] = *(const uint4*)&As[((ka * 8 + warp_m * 4 + ma) << 7) + lane * 4];
#pragma unroll
            for (int na = 0; na < 4; na++)
                *(uint2*)bf[na] = *(const uint2*)&Bs[((ka * 16 + warp_n * 4 + na) << 6) + lane * 2];
#pragma unroll
            for (int ma = 0; ma < 4; ma++)
#pragma unroll
                for (int na = 0; na < 4; na++) MMA_BF16(acc[ma][na], af[ma], bf[na]);
        }
        __syncthreads();
    }

    // epilogue: + a[b,m] + c[b,n]
    const int g = lane >> 2;
    const int tg = lane & 3;
#pragma unroll
    for (int ma = 0; ma < 4; ma++) {
        int r0 = m0 + warp_m * 64 + ma * 16 + g;
        float a0v = g_a[b * T_ + r0];
        float a1v = g_a[b * T_ + r0 + 8];
#pragma unroll
        for (int na = 0; na < 4; na++) {
            int n = n0 + warp_n * 32 + na * 8 + tg * 2;
            float c0 = g_c[b * J_ + n];
            float c1 = g_c[b * J_ + n + 1];
            float* p0 = g_S + (size_t)(b * T_ + r0) * J_ + n;
            *(float2*)p0 = make_float2(acc[ma][na][0] + a0v + c0, acc[ma][na][1] + a0v + c1);
            *(float2*)(p0 + 8 * J_) =
                make_float2(acc[ma][na][2] + a1v + c0, acc[ma][na][3] + a1v + c1);
        }
    }
}

// ---------------- kernel 3: rowmax over j -----------------------------------
__global__ __launch_bounds__(256) void rowmax_kernel() {
    int gw = (blockIdx.x * 256 + threadIdx.x) >> 5;
    int lane = threadIdx.x & 31;
    const float4* p = (const float4*)(g_S + (size_t)gw * J_);
    float4 v1 = p[lane];
    float4 v2 = p[lane + 32];
    float mx = fmaxf(fmaxf(fmaxf(v1.x, v1.y), fmaxf(v1.z, v1.w)),
                     fmaxf(fmaxf(v2.x, v2.y), fmaxf(v2.z, v2.w)));
#pragma unroll
    for (int off = 16; off > 0; off >>= 1) mx = fmaxf(mx, __shfl_xor_sync(0xffffffffu, mx, off));
    if (lane == 0) g_m[gw] = mx;
}

// ---------------- kernel 4: b_t = softmax_t(rowmax) -------------------------
__global__ __launch_bounds__(256) void bt_kernel() {
    const int b = blockIdx.x;
    const int tid = threadIdx.x;
    const int lane = tid & 31;
    const int wid = tid >> 5;
    __shared__ float redA[8], redB[8];

    float4 v = ((const float4*)(g_m + b * T_))[tid];
    float mx = fmaxf(fmaxf(v.x, v.y), fmaxf(v.z, v.w));
#pragma unroll
    for (int off = 16; off > 0; off >>= 1) mx = fmaxf(mx, __shfl_xor_sync(0xffffffffu, mx, off));
    if (lane == 0) redA[wid] = mx;
    __syncthreads();
    float bm = redA[0];
#pragma unroll
    for (int w = 1; w < 8; w++) bm = fmaxf(bm, redA[w]);

    float e0 = __expf(v.x - bm), e1 = __expf(v.y - bm);
    float e2 = __expf(v.z - bm), e3 = __expf(v.w - bm);
    float s = e0 + e1 + e2 + e3;
#pragma unroll
    for (int off = 16; off > 0; off >>= 1) s += __shfl_xor_sync(0xffffffffu, s, off);
    if (lane == 0) redB[wid] = s;
    __syncthreads();
    float tot = 0.f;
#pragma unroll
    for (int w = 0; w < 8; w++) tot += redB[w];
    float inv = 1.f / tot;
    ((float4*)(g_bt + b * T_))[tid] = make_float4(e0 * inv, e1 * inv, e2 * inv, e3 * inv);
}

// ---------------- kernel 5: column softmax over t (in place -> P) -----------
__global__ __launch_bounds__(256) void colsoftmax_kernel() {
    const int b = blockIdx.y;
    const int lane = threadIdx.x & 31;
    const int j = blockIdx.x * 32 + lane;
    const int ts = threadIdx.x >> 5;  // 0..7
    float* S = g_S + (size_t)b * T_ * J_;

    float mx = -3.0e38f, sm = 0.f;
    for (int t = ts; t < T_; t += 8) {
        float v = S[t * J_ + j];
        float nm = fmaxf(mx, v);
        sm = sm * __expf(mx - nm) + __expf(v - nm);
        mx = nm;
    }
    __shared__ float sM[8][32], sS[8][32];
    sM[ts][lane] = mx;
    sS[ts][lane] = sm;
    __syncthreads();
    if (threadIdx.x < 32) {
        float M = sM[0][lane], SS = sS[0][lane];
#pragma unroll
        for (int r = 1; r < 8; r++) {
            float m2 = sM[r][lane], s2 = sS[r][lane];
            float nm = fmaxf(M, m2);
            SS = SS * __expf(M - nm) + s2 * __expf(m2 - nm);
            M = nm;
        }
        sM[0][lane] = M;
        sS[0][lane] = SS;
    }
    __syncthreads();
    float M = sM[0][lane];
    float inv = 1.f / sS[0][lane];
    for (int t = ts; t < T_; t += 8) {
        float v = S[t * J_ + j];
        S[t * J_ + j] = __expf(v - M) * inv;
    }
}

// ---------------- kernel 6: h[b,d] = sum_t bt * ctx -------------------------
__global__ __launch_bounds__(256) void h_kernel(const float* __restrict__ ctx) {
    const int b = blockIdx.y;
    const int d = blockIdx.x * 256 + threadIdx.x;
    __shared__ float bts[T_];
    for (int i = threadIdx.x; i < T_; i += 256) bts[i] = g_bt[b * T_ + i];
    __syncthreads();
    const float* cp = ctx + (size_t)b * T_ * D_ + d;
    float acc = 0.f;
#pragma unroll 4
    for (int t = 0; t < T_; t++) acc += bts[t] * cp[(size_t)t * D_];
    g_h[b * D_ + d] = acc;
}

// ---------------- kernel 7: GEMM2  U = P @ q  (bf16 mma), fused G assembly --
// Block 128(t) x 128(d), K = 256 (j), K-tile 32 (= 2 k16 steps).
__global__ __launch_bounds__(256) void gemm2_tc(const float* __restrict__ ctx,
                                                const float* __restrict__ q,
                                                float* __restrict__ out) {
    __shared__ uint32_t As[2 * 8 * 128];
    __shared__ uint32_t Bs[2 * 16 * 64];

    const int tid = threadIdx.x;
    const int b = blockIdx.z;
    const int m0 = blockIdx.y * 128;
    const int n0 = blockIdx.x * 128;
    const float* Ag = g_S + (size_t)b * T_ * J_;  // P [1024][256]
    const float* Bg = q + (size_t)b * J_ * D_;    // [256][512], n contiguous

    const int lane = tid & 31;
    const int wid = tid >> 5;
    const int warp_m = wid & 1;
    const int warp_n = wid >> 1;

    float acc[4][4][4];
#pragma unroll
    for (int i = 0; i < 4; i++)
#pragma unroll
        for (int j = 0; j < 4; j++)
#pragma unroll
            for (int k = 0; k < 4; k++) acc[i][j][k] = 0.f;

    float4 pa[4];
    float4 pb0[2], pb1[2];
#pragma unroll
    for (int i = 0; i < 4; i++) {
        int f = tid + i * 256;
        int m = f >> 3, k4 = f & 7;
        pa[i] = *(const float4*)(Ag + (size_t)(m0 + m) * J_ + k4 * 4);
    }
#pragma unroll
    for (int i = 0; i < 2; i++) {
        int f = tid + i * 256;
        int kp = f >> 5, n4 = f & 31;
        pb0[i] = *(const float4*)(Bg + (size_t)(kp * 2) * D_ + n0 + n4 * 4);
        pb1[i] = *(const float4*)(Bg + (size_t)(kp * 2 + 1) * D_ + n0 + n4 * 4);
    }

    const int KT = J_ / 32;
    for (int kt = 0; kt < KT; kt++) {
        // A scatter
#pragma unroll
        for (int i = 0; i < 4; i++) {
            int f = tid + i * 256;
            int m = f >> 3, k4 = f & 7;
            int ka = k4 >> 2;
            int kl = (k4 & 3) * 4;
            int slot = (kl >> 1) & 3;
            float4 v = pa[i];
            int r = m & 15;
            uint32_t* dst = As + ((ka * 8 + (m >> 4)) << 7) +
                            ((r & 7) * 4 + slot) * 4 + (r >> 3) + ((kl >= 8) ? 2 : 0);
            dst[0] = bf2(v.x, v.y);
            dst[4] = bf2(v.z, v.w);
        }
        // B scatter: k-pair rows packed into bf16x2 along k
#pragma unroll
        for (int i = 0; i < 2; i++) {
            int f = tid + i * 256;
            int kp = f >> 5, n4 = f & 31;   // kp in [0,16), n4 in [0,32)
            int ka = kp >> 3;
            int pl = kp & 7;
            int slot = pl & 3;
            int regk = pl >> 2;
            const float* r0 = &pb0[i].x;
            const float* r1 = &pb1[i].x;
#pragma unroll
            for (int jj = 0; jj < 4; jj++) {
                int n = n4 * 4 + jj;
                uint32_t* dst = Bs + ((ka * 16 + (n >> 3)) << 6) +
                                ((n & 7) * 4 + slot) * 2 + regk;
                dst[0] = bf2(r0[jj], r1[jj]);
            }
        }
        __syncthreads();
        if (kt + 1 < KT) {
#pragma unroll
            for (int i = 0; i < 4; i++) {
                int f = tid + i * 256;
                int m = f >> 3, k4 = f & 7;
                pa[i] = *(const float4*)(Ag + (size_t)(m0 + m) * J_ + (kt + 1) * 32 + k4 * 4);
            }
#pragma unroll
            for (int i = 0; i < 2; i++) {
                int f = tid + i * 256;
                int kp = f >> 5, n4 = f & 31;
                pb0[i] = *(const float4*)(Bg + (size_t)((kt + 1) * 32 + kp * 2) * D_ + n0 + n4 * 4);
                pb1[i] = *(const float4*)(Bg + (size_t)((kt + 1) * 32 + kp * 2 + 1) * D_ + n0 + n4 * 4);
            }
        }
#pragma unroll
        for (int ka = 0; ka < 2; ka++) {
            uint32_t af[4][4], bf[4][2];
#pragma unroll
            for (int ma = 0; ma < 4; ma++)
                *(uint4*)af[ma] = *(const uint4*)&As[((ka * 8 + warp_m * 4 + ma) << 7) + lane * 4];
#pragma unroll
            for (int na = 0; na < 4; na++)
                *(uint2*)bf[na] = *(const uint2*)&Bs[((ka * 16 + warp_n * 4 + na) << 6) + lane * 2];
#pragma unroll
            for (int ma = 0; ma < 4; ma++)
#pragma unroll
                for (int na = 0; na < 4; na++) MMA_BF16(acc[ma][na], af[ma], bf[na]);
        }
        __syncthreads();
    }

    // epilogue: G = [ctx | U | ctx*U | ctx*h]
    const int g = lane >> 2;
    const int tg = lane & 3;
#pragma unroll
    for (int ma = 0; ma < 4; ma++) {
        int r0 = m0 + warp_m * 64 + ma * 16 + g;
#pragma unroll
        for (int rr = 0; rr < 2; rr++) {
            int m = r0 + rr * 8;
            const float* crow = ctx + ((size_t)(b * T_ + m)) * D_;
            float* orow = out + ((size_t)(b * T_ + m)) * (4 * D_);
#pragma unroll
            for (int na = 0; na < 4; na++) {
                int n = n0 + warp_n * 32 + na * 8 + tg * 2;
                float2 cv = *(const float2*)(crow + n);
                float2 hv = *(const float2*)(g_h + b * D_ + n);
                float u0 = acc[ma][na][rr * 2 + 0];
                float u1 = acc[ma][na][rr * 2 + 1];
                *(float2*)(orow + n) = cv;
                *(float2*)(orow + D_ + n) = make_float2(u0, u1);
                *(float2*)(orow + 2 * D_ + n) = make_float2(cv.x * u0, cv.y * u1);
                *(float2*)(orow + 3 * D_ + n) = make_float2(cv.x * hv.x, cv.y * hv.y);
            }
        }
    }
}

// ---------------- launch -----------------------------------------------------
extern "C" void kernel_launch(void* const* d_in, const int* in_sizes, int n_in,
                              void* d_out, int out_size) {
    const float* ctx = (const float*)d_in[0];
    const float* q = (const float*)d_in[1];
    const float* w = (const float*)d_in[2];
    float* out = (float*)d_out;

    dotw_kernel<<<5120, 256>>>(ctx, q, w);
    gemm1_tc<<<dim3(2, 8, 32), 256>>>(ctx, q, w);
    rowmax_kernel<<<4096, 256>>>();
    bt_kernel<<<32, 256>>>();
    colsoftmax_kernel<<<dim3(8, 32), 256>>>();
    h_kernel<<<dim3(2, 32), 256>>>(ctx);
    gemm2_tc<<<dim3(4, 8, 32), 256>>>(ctx, q, out);
}